// round 9
// baseline (speedup 1.0000x reference)
#include <cuda_runtime.h>
#include <cuda_fp16.h>

#define NUM_USERS 100000
#define NUM_ITEMS 50000
#define N_NODES   150000
#define EMB_DIM   64
#define N_EDGES   4800000

#define VAL_BITS  14
#define VAL_MASK  ((1u << VAL_BITS) - 1u)          // 16383
#define VAL_SCALE ((float)VAL_MASK)
#define VAL_INV   (1.0f / VAL_SCALE)

#define SLOT_BITS 7
#define SLOTS     (1 << SLOT_BITS)                 // 128 slots/row (λ=32; P(overflow)≈0)

// Scratch (__device__ globals: allowed)
__device__ __half   g_h0[N_NODES * EMB_DIM];       // 19.2 MB fp16 embeddings (ping)
__device__ __half   g_h1[N_NODES * EMB_DIM];       // 19.2 MB fp16 embeddings (pong)
__device__ int      g_cursor[N_NODES];             // per-row edge count
__device__ unsigned g_pack[N_NODES << SLOT_BITS];  // ELL: (col<<14)|val_q14, 76.8 MB

// ---------------------------------------------------------------------------
// init: h0 = fp16(concat(user,item)); counts = 0   (acc NOT written)
// ---------------------------------------------------------------------------
__global__ void lgcn_init(const float* __restrict__ user_emb,
                          const float* __restrict__ item_emb) {
    int i = blockIdx.x * blockDim.x + threadIdx.x;   // float4 index
    const int total4 = N_NODES * EMB_DIM / 4;
    if (i < N_NODES) g_cursor[i] = 0;
    if (i >= total4) return;
    const int uend4 = NUM_USERS * EMB_DIM / 4;
    float4 v = (i < uend4) ? ((const float4*)user_emb)[i]
                           : ((const float4*)item_emb)[i - uend4];
    __half2 h01 = __floats2half2_rn(v.x, v.y);
    __half2 h23 = __floats2half2_rn(v.z, v.w);
    ((uint2*)g_h0)[i] = make_uint2(*(unsigned*)&h01, *(unsigned*)&h23);
}

// ---------------------------------------------------------------------------
// scatter edges into ELL bins (4 edges / thread, vectorized reads)
// ---------------------------------------------------------------------------
__global__ void lgcn_scatter(const float* __restrict__ vals,
                             const int*   __restrict__ rows,
                             const int*   __restrict__ cols) {
    int i = blockIdx.x * blockDim.x + threadIdx.x;
    if (i >= N_EDGES / 4) return;
    int4   r = ((const int4*)rows)[i];
    int4   c = ((const int4*)cols)[i];
    float4 v = ((const float4*)vals)[i];
    {
        unsigned w = ((unsigned)c.x << VAL_BITS) | (unsigned)__float2int_rn(v.x * VAL_SCALE);
        g_pack[((unsigned)r.x << SLOT_BITS) + atomicAdd(&g_cursor[r.x], 1)] = w;
    }
    {
        unsigned w = ((unsigned)c.y << VAL_BITS) | (unsigned)__float2int_rn(v.y * VAL_SCALE);
        g_pack[((unsigned)r.y << SLOT_BITS) + atomicAdd(&g_cursor[r.y], 1)] = w;
    }
    {
        unsigned w = ((unsigned)c.z << VAL_BITS) | (unsigned)__float2int_rn(v.z * VAL_SCALE);
        g_pack[((unsigned)r.z << SLOT_BITS) + atomicAdd(&g_cursor[r.z], 1)] = w;
    }
    {
        unsigned w = ((unsigned)c.w << VAL_BITS) | (unsigned)__float2int_rn(v.w * VAL_SCALE);
        g_pack[((unsigned)r.w << SLOT_BITS) + atomicAdd(&g_cursor[r.w], 1)] = w;
    }
}

// ---------------------------------------------------------------------------
// pad: round each row's count up to even with a zero edge (col=0, val=0)
// ---------------------------------------------------------------------------
__global__ void lgcn_pad() {
    int i = blockIdx.x * blockDim.x + threadIdx.x;
    if (i >= N_NODES) return;
    int cnt = g_cursor[i];
    if (cnt & 1) {
        g_pack[(i << SLOT_BITS) + cnt] = 0u;   // val_q=0 -> contributes nothing
        g_cursor[i] = cnt + 1;
    }
}

// ---------------------------------------------------------------------------
// fp16 ELL SpMM core: 4 threads/row, each lane owns 16 halves (2 x uint4).
// Pack words read 2-at-a-time (uint2). Counts are even (padded): no tail.
// fp32 accumulation.
// ---------------------------------------------------------------------------
__device__ __forceinline__ void fma8(float* s, const uint4& a, float v) {
    const __half2* ph = (const __half2*)&a;
    #pragma unroll
    for (int k = 0; k < 4; k++) {
        float2 f = __half22float2(ph[k]);
        s[2*k]   += v * f.x;
        s[2*k+1] += v * f.y;
    }
}

__device__ __forceinline__ void spmm_row(const uint4* __restrict__ x4,
                                         int row, int lane, float* s) {
    int p   = row << SLOT_BITS;
    int end = p + g_cursor[row];             // even
    for (; p < end; p += 2) {
        uint2 ww = *(const uint2*)&g_pack[p];   // aligned: p even, base 128-aligned
        int i0 = (int)(ww.x >> VAL_BITS) * 8 + lane * 2;
        int i1 = (int)(ww.y >> VAL_BITS) * 8 + lane * 2;
        uint4 a0 = __ldg(&x4[i0]);
        uint4 a1 = __ldg(&x4[i0 + 1]);
        uint4 b0 = __ldg(&x4[i1]);
        uint4 b1 = __ldg(&x4[i1 + 1]);
        float v0 = (float)(ww.x & VAL_MASK) * VAL_INV;
        float v1 = (float)(ww.y & VAL_MASK) * VAL_INV;
        fma8(s,     a0, v0);
        fma8(s + 8, a1, v0);
        fma8(s,     b0, v1);
        fma8(s + 8, b1, v1);
    }
}

__device__ __forceinline__ uint4 to_h16(const float* s) {
    __half2 h0 = __floats2half2_rn(s[0], s[1]);
    __half2 h1 = __floats2half2_rn(s[2], s[3]);
    __half2 h2 = __floats2half2_rn(s[4], s[5]);
    __half2 h3 = __floats2half2_rn(s[6], s[7]);
    uint4 out;
    out.x = *(unsigned*)&h0; out.y = *(unsigned*)&h1;
    out.z = *(unsigned*)&h2; out.w = *(unsigned*)&h3;
    return out;
}

// layers 1-2: y(fp16) = A x, no acc traffic
__global__ void lgcn_spmm_mid(const __half* __restrict__ x,
                              __half* __restrict__ y) {
    int t = blockIdx.x * blockDim.x + threadIdx.x;
    int row  = t >> 2;
    int lane = t & 3;
    if (row >= N_NODES) return;

    float s[16];
    #pragma unroll
    for (int k = 0; k < 16; k++) s[k] = 0.f;
    spmm_row((const uint4*)x, row, lane, s);

    uint4* y4 = (uint4*)y;
    int o = row * 8 + lane * 2;
    y4[o]     = to_h16(s);
    y4[o + 1] = to_h16(s + 8);
}

// layer 3: s = A e2; acc = (x0 + e1 + e2 + s) * 0.25, acc write-only
//   x0 read from fp32 inputs, e1 = g_h1, e2 = g_h0 (also gather input)
__global__ void lgcn_spmm_final(const __half* __restrict__ e2buf,
                                const __half* __restrict__ e1buf,
                                const float* __restrict__ user_emb,
                                const float* __restrict__ item_emb,
                                float* __restrict__ acc) {
    int t = blockIdx.x * blockDim.x + threadIdx.x;
    int row  = t >> 2;
    int lane = t & 3;
    if (row >= N_NODES) return;

    float s[16];
    #pragma unroll
    for (int k = 0; k < 16; k++) s[k] = 0.f;
    spmm_row((const uint4*)e2buf, row, lane, s);

    // add own-row e1 + e2 (fp16): lane owns uint4 slots row*8+lane*2, +1
    int ho = row * 8 + lane * 2;
    uint4 e1a = ((const uint4*)e1buf)[ho];
    uint4 e1b = ((const uint4*)e1buf)[ho + 1];
    uint4 e2a = ((const uint4*)e2buf)[ho];
    uint4 e2b = ((const uint4*)e2buf)[ho + 1];
    fma8(s,     e1a, 1.0f);
    fma8(s + 8, e1b, 1.0f);
    fma8(s,     e2a, 1.0f);
    fma8(s + 8, e2b, 1.0f);

    // x0 from original fp32 inputs: lane owns float4 slots row*16 + lane*4 .. +3
    const float4* src4 = (row < NUM_USERS)
        ? (const float4*)user_emb + (size_t)row * 16
        : (const float4*)item_emb + (size_t)(row - NUM_USERS) * 16;

    float4* acc4 = (float4*)acc;
    int o = row * 16 + lane * 4;
    #pragma unroll
    for (int j = 0; j < 4; j++) {
        float4 a = src4[lane * 4 + j];
        acc4[o + j] = make_float4((a.x + s[4*j + 0]) * 0.25f,
                                  (a.y + s[4*j + 1]) * 0.25f,
                                  (a.z + s[4*j + 2]) * 0.25f,
                                  (a.w + s[4*j + 3]) * 0.25f);
    }
}

extern "C" void kernel_launch(void* const* d_in, const int* in_sizes, int n_in,
                              void* d_out, int out_size) {
    const float* user_emb = (const float*)d_in[0];
    const float* item_emb = (const float*)d_in[1];
    const float* adj_vals = (const float*)d_in[2];
    const int*   adj_rows = (const int*)  d_in[3];
    const int*   adj_cols = (const int*)  d_in[4];
    float*       acc      = (float*)d_out;

    __half *h0, *h1;
    cudaGetSymbolAddress((void**)&h0, g_h0);
    cudaGetSymbolAddress((void**)&h1, g_h1);

    const int total4  = N_NODES * EMB_DIM / 4;                 // 2.4M
    const int ew_grid = (total4 + 255) / 256;
    const int sc_grid = (N_EDGES / 4 + 255) / 256;
    const int n_grid  = (N_NODES + 255) / 256;
    const int sp_grid = (N_NODES * 4 + 255) / 256;             // 4 thr/row

    // h0 = fp16(x0); counts = 0
    lgcn_init<<<ew_grid, 256>>>(user_emb, item_emb);

    // ELL build + even-pad
    lgcn_scatter<<<sc_grid, 256>>>(adj_vals, adj_rows, adj_cols);
    lgcn_pad<<<n_grid, 256>>>();

    // layer 1: e1 = A x0        (h0 -> h1)
    lgcn_spmm_mid<<<sp_grid, 256>>>(h0, h1);
    // layer 2: e2 = A e1        (h1 -> h0)
    lgcn_spmm_mid<<<sp_grid, 256>>>(h1, h0);
    // layer 3: acc = (x0 + e1 + e2 + A e2) / 4
    lgcn_spmm_final<<<sp_grid, 256>>>(h0, h1, user_emb, item_emb, acc);
}

// round 10
// speedup vs baseline: 1.1323x; 1.1323x over previous
#include <cuda_runtime.h>
#include <cuda_fp16.h>

#define NUM_USERS 100000
#define NUM_ITEMS 50000
#define N_NODES   150000
#define EMB_DIM   64
#define N_EDGES   4800000

#define VAL_BITS  14
#define VAL_MASK  ((1u << VAL_BITS) - 1u)          // 16383
#define VAL_SCALE ((float)VAL_MASK)
#define VAL_INV   (1.0f / VAL_SCALE)

#define SLOT_BITS 7
#define SLOTS     (1 << SLOT_BITS)                 // 128 slots/row (λ=32; P(overflow)≈0)

// Scratch (__device__ globals: allowed)
__device__ __half   g_h0[N_NODES * EMB_DIM];       // 19.2 MB fp16 embeddings (ping)
__device__ __half   g_h1[N_NODES * EMB_DIM];       // 19.2 MB fp16 embeddings (pong)
__device__ int      g_cursor[N_NODES];             // per-row edge count
__device__ unsigned g_pack[N_NODES << SLOT_BITS];  // ELL: (col<<14)|val_q14, 76.8 MB

// ---------------------------------------------------------------------------
// init: h0 = fp16(concat(user,item)); counts = 0   (acc NOT written)
// ---------------------------------------------------------------------------
__global__ void lgcn_init(const float* __restrict__ user_emb,
                          const float* __restrict__ item_emb) {
    int i = blockIdx.x * blockDim.x + threadIdx.x;   // float4 index
    const int total4 = N_NODES * EMB_DIM / 4;
    if (i < N_NODES) g_cursor[i] = 0;
    if (i >= total4) return;
    const int uend4 = NUM_USERS * EMB_DIM / 4;
    float4 v = (i < uend4) ? ((const float4*)user_emb)[i]
                           : ((const float4*)item_emb)[i - uend4];
    __half2 h01 = __floats2half2_rn(v.x, v.y);
    __half2 h23 = __floats2half2_rn(v.z, v.w);
    ((uint2*)g_h0)[i] = make_uint2(*(unsigned*)&h01, *(unsigned*)&h23);
}

// ---------------------------------------------------------------------------
// scatter edges into ELL bins (4 edges / thread, vectorized reads)
// ---------------------------------------------------------------------------
__global__ void lgcn_scatter(const float* __restrict__ vals,
                             const int*   __restrict__ rows,
                             const int*   __restrict__ cols) {
    int i = blockIdx.x * blockDim.x + threadIdx.x;
    if (i >= N_EDGES / 4) return;
    int4   r = ((const int4*)rows)[i];
    int4   c = ((const int4*)cols)[i];
    float4 v = ((const float4*)vals)[i];
    {
        unsigned w = ((unsigned)c.x << VAL_BITS) | (unsigned)__float2int_rn(v.x * VAL_SCALE);
        g_pack[((unsigned)r.x << SLOT_BITS) + atomicAdd(&g_cursor[r.x], 1)] = w;
    }
    {
        unsigned w = ((unsigned)c.y << VAL_BITS) | (unsigned)__float2int_rn(v.y * VAL_SCALE);
        g_pack[((unsigned)r.y << SLOT_BITS) + atomicAdd(&g_cursor[r.y], 1)] = w;
    }
    {
        unsigned w = ((unsigned)c.z << VAL_BITS) | (unsigned)__float2int_rn(v.z * VAL_SCALE);
        g_pack[((unsigned)r.z << SLOT_BITS) + atomicAdd(&g_cursor[r.z], 1)] = w;
    }
    {
        unsigned w = ((unsigned)c.w << VAL_BITS) | (unsigned)__float2int_rn(v.w * VAL_SCALE);
        g_pack[((unsigned)r.w << SLOT_BITS) + atomicAdd(&g_cursor[r.w], 1)] = w;
    }
}

// ---------------------------------------------------------------------------
// pad: round each row's count up to a multiple of 4 with zero edges
// (col=0, val_q=0 -> contributes exactly nothing)
// ---------------------------------------------------------------------------
__global__ void lgcn_pad() {
    int i = blockIdx.x * blockDim.x + threadIdx.x;
    if (i >= N_NODES) return;
    int cnt = g_cursor[i];
    int padded = (cnt + 3) & ~3;
    for (int p = cnt; p < padded; p++)
        g_pack[(i << SLOT_BITS) + p] = 0u;
    if (padded != cnt) g_cursor[i] = padded;
}

// ---------------------------------------------------------------------------
// fp16 ELL SpMM core: 8 threads/row, one uint4 gather per edge per lane,
// pack words loaded 4-at-a-time (uint4; counts padded to 4 -> no tail),
// fp32 accumulation.
// ---------------------------------------------------------------------------
__device__ __forceinline__ void fma8(float* s, const uint4& a, float v) {
    const __half2* ph = (const __half2*)&a;
    #pragma unroll
    for (int k = 0; k < 4; k++) {
        float2 f = __half22float2(ph[k]);
        s[2*k]   += v * f.x;
        s[2*k+1] += v * f.y;
    }
}

__device__ __forceinline__ void spmm_row(const uint4* __restrict__ x4,
                                         int row, int lane, float* s) {
    int p   = row << SLOT_BITS;
    int end = p + g_cursor[row];             // multiple of 4
    for (; p < end; p += 4) {
        uint4 ww = *(const uint4*)&g_pack[p];   // aligned: p % 4 == 0, base 512B-aligned
        uint4 a0 = __ldg(&x4[(ww.x >> VAL_BITS) * 8 + lane]);
        uint4 a1 = __ldg(&x4[(ww.y >> VAL_BITS) * 8 + lane]);
        uint4 a2 = __ldg(&x4[(ww.z >> VAL_BITS) * 8 + lane]);
        uint4 a3 = __ldg(&x4[(ww.w >> VAL_BITS) * 8 + lane]);
        fma8(s, a0, (float)(ww.x & VAL_MASK) * VAL_INV);
        fma8(s, a1, (float)(ww.y & VAL_MASK) * VAL_INV);
        fma8(s, a2, (float)(ww.z & VAL_MASK) * VAL_INV);
        fma8(s, a3, (float)(ww.w & VAL_MASK) * VAL_INV);
    }
}

// layers 1-2: y(fp16) = A x, no acc traffic
__global__ void lgcn_spmm_mid(const __half* __restrict__ x,
                              __half* __restrict__ y) {
    int t = blockIdx.x * blockDim.x + threadIdx.x;
    int row  = t >> 3;
    int lane = t & 7;
    if (row >= N_NODES) return;

    float s[8] = {0.f, 0.f, 0.f, 0.f, 0.f, 0.f, 0.f, 0.f};
    spmm_row((const uint4*)x, row, lane, s);

    __half2 h0 = __floats2half2_rn(s[0], s[1]);
    __half2 h1 = __floats2half2_rn(s[2], s[3]);
    __half2 h2 = __floats2half2_rn(s[4], s[5]);
    __half2 h3 = __floats2half2_rn(s[6], s[7]);
    uint4 out;
    out.x = *(unsigned*)&h0; out.y = *(unsigned*)&h1;
    out.z = *(unsigned*)&h2; out.w = *(unsigned*)&h3;
    ((uint4*)y)[row * 8 + lane] = out;
}

// layer 3: s = A e2; acc = (x0 + e1 + e2 + s) * 0.25, acc write-only
//   x0 read from fp32 inputs, e1 = g_h1, e2 = g_h0 (also gather input)
__global__ void lgcn_spmm_final(const __half* __restrict__ e2buf,
                                const __half* __restrict__ e1buf,
                                const float* __restrict__ user_emb,
                                const float* __restrict__ item_emb,
                                float* __restrict__ acc) {
    int t = blockIdx.x * blockDim.x + threadIdx.x;
    int row  = t >> 3;
    int lane = t & 7;
    if (row >= N_NODES) return;

    float s[8] = {0.f, 0.f, 0.f, 0.f, 0.f, 0.f, 0.f, 0.f};
    spmm_row((const uint4*)e2buf, row, lane, s);

    // add own-row e1 + e2 (fp16)
    uint4 e1w = ((const uint4*)e1buf)[row * 8 + lane];
    uint4 e2w = ((const uint4*)e2buf)[row * 8 + lane];
    fma8(s, e1w, 1.0f);
    fma8(s, e2w, 1.0f);

    // x0 from original fp32 inputs
    const float4* src4 = (row < NUM_USERS)
        ? (const float4*)user_emb + (size_t)row * 16
        : (const float4*)item_emb + (size_t)(row - NUM_USERS) * 16;
    float4 a0 = src4[lane * 2];
    float4 a1 = src4[lane * 2 + 1];

    float4* acc4 = (float4*)acc;
    int o = row * 16 + lane * 2;
    acc4[o]     = make_float4((a0.x + s[0]) * 0.25f, (a0.y + s[1]) * 0.25f,
                              (a0.z + s[2]) * 0.25f, (a0.w + s[3]) * 0.25f);
    acc4[o + 1] = make_float4((a1.x + s[4]) * 0.25f, (a1.y + s[5]) * 0.25f,
                              (a1.z + s[6]) * 0.25f, (a1.w + s[7]) * 0.25f);
}

extern "C" void kernel_launch(void* const* d_in, const int* in_sizes, int n_in,
                              void* d_out, int out_size) {
    const float* user_emb = (const float*)d_in[0];
    const float* item_emb = (const float*)d_in[1];
    const float* adj_vals = (const float*)d_in[2];
    const int*   adj_rows = (const int*)  d_in[3];
    const int*   adj_cols = (const int*)  d_in[4];
    float*       acc      = (float*)d_out;

    __half *h0, *h1;
    cudaGetSymbolAddress((void**)&h0, g_h0);
    cudaGetSymbolAddress((void**)&h1, g_h1);

    const int total4  = N_NODES * EMB_DIM / 4;                 // 2.4M
    const int ew_grid = (total4 + 255) / 256;
    const int sc_grid = (N_EDGES / 4 + 255) / 256;
    const int n_grid  = (N_NODES + 255) / 256;
    const int sp_grid = (N_NODES * 8 + 255) / 256;             // 8 thr/row

    // h0 = fp16(x0); counts = 0
    lgcn_init<<<ew_grid, 256>>>(user_emb, item_emb);

    // ELL build + pad counts to multiple of 4
    lgcn_scatter<<<sc_grid, 256>>>(adj_vals, adj_rows, adj_cols);
    lgcn_pad<<<n_grid, 256>>>();

    // layer 1: e1 = A x0        (h0 -> h1)
    lgcn_spmm_mid<<<sp_grid, 256>>>(h0, h1);
    // layer 2: e2 = A e1        (h1 -> h0)
    lgcn_spmm_mid<<<sp_grid, 256>>>(h1, h0);
    // layer 3: acc = (x0 + e1 + e2 + A e2) / 4
    lgcn_spmm_final<<<sp_grid, 256>>>(h0, h1, user_emb, item_emb, acc);
}